// round 4
// baseline (speedup 1.0000x reference)
#include <cuda_runtime.h>
#include <math.h>

// Problem constants
#define BATCH   4096
#define VOCABSZ 100000
#define EMBDIM  64
#define D_IN    256
#define D_H     256
#define D_OUT   128
#define N_NEG4  4      // n_neg + 1

// Scratch for tower outputs (u then v), 2 * 4096 * 128 floats = 4 MB
__device__ float g_uv[2u * BATCH * D_OUT];

// Tiling
constexpr int TM        = 64;   // rows per block
constexpr int XS_STRIDE = 68;   // padded stride for transposed X/H tile [256][68]
constexpr int SMEM_FLOATS = D_H * XS_STRIDE + 32 * D_H;   // Xs + W-tile
// Xs: 256*68*4 = 69,632 B ; Ws: 32*256*4 = 32,768 B ; total 102,400 B

__global__ __launch_bounds__(256, 1)
void tower_kernel(const int* __restrict__ user_ids, const int* __restrict__ item_ids,
                  const float* __restrict__ user_tables, const float* __restrict__ item_tables,
                  const float* __restrict__ uW1, const float* __restrict__ ub1,
                  const float* __restrict__ uW2, const float* __restrict__ ub2,
                  const float* __restrict__ iW1, const float* __restrict__ ib1,
                  const float* __restrict__ iW2, const float* __restrict__ ib2)
{
    extern __shared__ float smem[];
    float* Xs = smem;                      // [256][68] transposed: Xs[k][row]
    float* Ws = smem + D_H * XS_STRIDE;    // [32][256] (GEMM1) / [32][128] (GEMM2)

    const int tower  = blockIdx.x >> 6;    // 0 = user, 1 = item
    const int rowblk = blockIdx.x & 63;

    const int*   ids = tower ? item_ids    : user_ids;
    const float* tbl = tower ? item_tables : user_tables;
    const float* W1  = tower ? iW1 : uW1;
    const float* b1  = tower ? ib1 : ub1;
    const float* W2  = tower ? iW2 : uW2;
    const float* b2  = tower ? ib2 : ub2;
    float* gout = g_uv + (size_t)tower * BATCH * D_OUT;

    const int tid  = threadIdx.x;          // 256 threads
    const int x    = tid & 15;             // 16 col-groups
    const int y    = tid >> 4;             // 16 row-groups (4 rows each)
    const int row0 = rowblk * TM;

    // ---------------- Embedding gather (transposed into Xs) ----------------
    // X[row][c] with c = f*64 + e ; thread owns column c = tid for all 64 rows.
    {
        const int f = tid >> 6;            // feature 0..3
        const int e = tid & 63;            // dim within feature
        const float* tf = tbl + (size_t)f * VOCABSZ * EMBDIM + e;
        const int* idp = ids + f;
        #pragma unroll 4
        for (int r = 0; r < TM; ++r) {
            int id = __ldg(&idp[(row0 + r) * 4]);
            Xs[tid * XS_STRIDE + r] = __ldg(&tf[(size_t)id * EMBDIM]);
        }
    }
    __syncthreads();

    // ---------------- GEMM1: H[64,256] = relu(X @ W1 + b1) ----------------
    float acc[4][16];
    #pragma unroll
    for (int r = 0; r < 4; ++r)
        #pragma unroll
        for (int j = 0; j < 16; ++j) acc[r][j] = 0.f;

    for (int kt = 0; kt < D_IN; kt += 32) {
        __syncthreads();   // previous W tile fully consumed
        // Load W1 tile [32][256] (8192 floats, 8 float4 per thread, coalesced)
        #pragma unroll
        for (int i = tid; i < 32 * 64; i += 256) {
            int kr = i >> 6, nc = (i & 63) << 2;
            *(float4*)&Ws[kr * 256 + nc] = *(const float4*)&W1[(kt + kr) * 256 + nc];
        }
        __syncthreads();
        #pragma unroll 8
        for (int k = 0; k < 32; ++k) {
            float4 xv = *(const float4*)&Xs[(kt + k) * XS_STRIDE + 4 * y];
            #pragma unroll
            for (int j = 0; j < 16; ++j) {
                float w = Ws[k * 256 + x + 16 * j];
                acc[0][j] = fmaf(xv.x, w, acc[0][j]);
                acc[1][j] = fmaf(xv.y, w, acc[1][j]);
                acc[2][j] = fmaf(xv.z, w, acc[2][j]);
                acc[3][j] = fmaf(xv.w, w, acc[3][j]);
            }
        }
    }
    __syncthreads();

    // bias + relu, store H transposed back into Xs (X no longer needed)
    #pragma unroll
    for (int j = 0; j < 16; ++j) {
        int n = x + 16 * j;
        float bb = __ldg(&b1[n]);
        #pragma unroll
        for (int r = 0; r < 4; ++r)
            Xs[n * XS_STRIDE + 4 * y + r] = fmaxf(acc[r][j] + bb, 0.f);
    }
    __syncthreads();

    // ---------------- GEMM2: U[64,128] = relu(H @ W2 + b2) ----------------
    float acc2[4][8];
    #pragma unroll
    for (int r = 0; r < 4; ++r)
        #pragma unroll
        for (int j = 0; j < 8; ++j) acc2[r][j] = 0.f;

    for (int kt = 0; kt < D_H; kt += 32) {
        __syncthreads();
        // Load W2 tile [32][128] (4096 floats, 4 float4 per thread)
        #pragma unroll
        for (int i = tid; i < 32 * 32; i += 256) {
            int kr = i >> 5, nc = (i & 31) << 2;
            *(float4*)&Ws[kr * 128 + nc] = *(const float4*)&W2[(kt + kr) * 128 + nc];
        }
        __syncthreads();
        #pragma unroll 8
        for (int k = 0; k < 32; ++k) {
            float4 hv = *(const float4*)&Xs[(kt + k) * XS_STRIDE + 4 * y];
            #pragma unroll
            for (int j = 0; j < 8; ++j) {
                float w = Ws[k * 128 + x + 16 * j];
                acc2[0][j] = fmaf(hv.x, w, acc2[0][j]);
                acc2[1][j] = fmaf(hv.y, w, acc2[1][j]);
                acc2[2][j] = fmaf(hv.z, w, acc2[2][j]);
                acc2[3][j] = fmaf(hv.w, w, acc2[3][j]);
            }
        }
    }

    // bias + relu, store raw (unnormalized) tower output to global scratch
    #pragma unroll
    for (int j = 0; j < 8; ++j) {
        int n = x + 16 * j;
        float bb = __ldg(&b2[n]);
        #pragma unroll
        for (int r = 0; r < 4; ++r)
            gout[(size_t)(row0 + 4 * y + r) * D_OUT + n] = fmaxf(acc2[r][j] + bb, 0.f);
    }
}

// ---------------- Scoring: banded cosine sim + debias ----------------
// out[i][j] = dot(u_i, v_c) / (max(|u_i|,eps)*max(|v_c|,eps)) - log(sw[sw_ids[c]]),
// c = (i + j) mod B.  One warp per output row.
__global__ __launch_bounds__(256)
void score_kernel(const int* __restrict__ sw_ids, const float* __restrict__ sw_table,
                  float* __restrict__ out)
{
    int gw   = (blockIdx.x * blockDim.x + threadIdx.x) >> 5;
    int lane = threadIdx.x & 31;
    if (gw >= BATCH) return;

    const float* u = g_uv + (size_t)gw * D_OUT;
    float4 uv = *(const float4*)&u[lane * 4];
    float su = uv.x*uv.x + uv.y*uv.y + uv.z*uv.z + uv.w*uv.w;
    #pragma unroll
    for (int o = 16; o; o >>= 1) su += __shfl_xor_sync(0xffffffffu, su, o);
    float inv_nu = 1.f / fmaxf(sqrtf(su), 1e-8f);

    #pragma unroll
    for (int j = 0; j < N_NEG4; ++j) {
        int col = (gw + j) & (BATCH - 1);
        const float* v = g_uv + (size_t)BATCH * D_OUT + (size_t)col * D_OUT;
        float4 vv = *(const float4*)&v[lane * 4];
        float d  = uv.x*vv.x + uv.y*vv.y + uv.z*vv.z + uv.w*vv.w;
        float sv = vv.x*vv.x + vv.y*vv.y + vv.z*vv.z + vv.w*vv.w;
        #pragma unroll
        for (int o = 16; o; o >>= 1) {
            d  += __shfl_xor_sync(0xffffffffu, d,  o);
            sv += __shfl_xor_sync(0xffffffffu, sv, o);
        }
        if (lane == 0) {
            float pred = d * inv_nu / fmaxf(sqrtf(sv), 1e-8f);
            out[gw * N_NEG4 + j] = pred - logf(__ldg(&sw_table[__ldg(&sw_ids[col])]));
        }
    }
}

extern "C" void kernel_launch(void* const* d_in, const int* in_sizes, int n_in,
                              void* d_out, int out_size)
{
    const int*   user_ids    = (const int*)  d_in[0];
    const int*   item_ids    = (const int*)  d_in[1];
    const int*   sw_ids      = (const int*)  d_in[2];
    const float* user_tables = (const float*)d_in[3];
    const float* item_tables = (const float*)d_in[4];
    const float* sw_table    = (const float*)d_in[5];
    const float* uW1 = (const float*)d_in[6];
    const float* ub1 = (const float*)d_in[7];
    const float* uW2 = (const float*)d_in[8];
    const float* ub2 = (const float*)d_in[9];
    const float* iW1 = (const float*)d_in[10];
    const float* ib1 = (const float*)d_in[11];
    const float* iW2 = (const float*)d_in[12];
    const float* ib2 = (const float*)d_in[13];
    (void)in_sizes; (void)n_in; (void)out_size;

    const int smem_bytes = SMEM_FLOATS * (int)sizeof(float);   // 102,400 B
    cudaFuncSetAttribute(tower_kernel, cudaFuncAttributeMaxDynamicSharedMemorySize,
                         smem_bytes);

    // 64 row-tiles x 2 towers
    tower_kernel<<<128, 256, smem_bytes>>>(user_ids, item_ids,
                                           user_tables, item_tables,
                                           uW1, ub1, uW2, ub2,
                                           iW1, ib1, iW2, ib2);
    // 4096 rows, one warp each -> 512 blocks of 8 warps
    score_kernel<<<512, 256>>>(sw_ids, sw_table, (float*)d_out);
}

// round 5
// speedup vs baseline: 1.7146x; 1.7146x over previous
#include <cuda_runtime.h>
#include <math.h>

// Problem constants
#define BATCH   4096
#define VOCABSZ 100000
#define EMBDIM  64
#define D_IN    256
#define D_H     256
#define D_OUT   128
#define N_NEG4  4

// Scratch: NORMALIZED tower outputs (u then v), 2 * 4096 * 128 floats = 4 MB
__device__ float g_uv[2u * BATCH * D_OUT];

// Tiling
constexpr int TM   = 64;     // rows per block
constexpr int STR2 = 132;    // floats per k-slot: 2*64 duplicated + 4 pad (16B-aligned stride)
constexpr int XS_FLOATS   = 256 * STR2;          // 33792 floats = 135168 B
constexpr int WS_FLOATS   = 32 * 256;            //  8192 floats =  32768 B
constexpr int SMEM_FLOATS = XS_FLOATS + WS_FLOATS;

// Packed fp32 FMA2: d = a*b + d on two lanes of a 64-bit register (sm_100+)
#define FMA2(acc, a, b) \
    asm("fma.rn.f32x2 %0, %1, %2, %0;" : "+l"(acc) : "l"(a), "l"(b))

__global__ __launch_bounds__(256, 1)
void tower_kernel(const int* __restrict__ user_ids, const int* __restrict__ item_ids,
                  const float* __restrict__ user_tables, const float* __restrict__ item_tables,
                  const float* __restrict__ uW1, const float* __restrict__ ub1,
                  const float* __restrict__ uW2, const float* __restrict__ ub2,
                  const float* __restrict__ iW1, const float* __restrict__ ib1,
                  const float* __restrict__ iW2, const float* __restrict__ ib2)
{
    extern __shared__ float smem[];
    float* Xs = smem;                 // duplicated [256][STR2] : Xs[k][2r]=Xs[k][2r+1]=X[r][k]
    float* Ws = smem + XS_FLOATS;     // [32][256] (GEMM1) / [32][128] (GEMM2)

    const int tower  = blockIdx.x >> 6;
    const int rowblk = blockIdx.x & 63;

    const int*   ids = tower ? item_ids    : user_ids;
    const float* tbl = tower ? item_tables : user_tables;
    const float* W1  = tower ? iW1 : uW1;
    const float* b1  = tower ? ib1 : ub1;
    const float* W2  = tower ? iW2 : uW2;
    const float* b2  = tower ? ib2 : ub2;
    float* gout = g_uv + (size_t)tower * BATCH * D_OUT;

    const int tid  = threadIdx.x;
    const int x    = tid & 15;        // column-pair group
    const int y    = tid >> 4;        // row group (4 rows)
    const int row0 = rowblk * TM;

    // ---------------- Embedding gather (duplicated, transposed) ----------------
    {
        const int f = tid >> 6;
        const int e = tid & 63;
        const float* tf = tbl + (size_t)f * VOCABSZ * EMBDIM + e;
        const int* idp = ids + f;
        float* xc = &Xs[tid * STR2];
        #pragma unroll 4
        for (int r = 0; r < TM; ++r) {
            int id  = __ldg(&idp[(row0 + r) * 4]);
            float v = __ldg(&tf[(size_t)id * EMBDIM]);
            *(float2*)&xc[2 * r] = make_float2(v, v);
        }
    }
    __syncthreads();

    // ---------------- GEMM1: H[64,256] = relu(X @ W1 + b1), FFMA2 ----------------
    unsigned long long acc[4][8] = {};   // acc[p][j] = {row(4y+p) x col(2x+32j), col+1}

    for (int kt = 0; kt < D_IN; kt += 32) {
        __syncthreads();
        #pragma unroll
        for (int i = tid; i < 32 * 64; i += 256) {
            int kr = i >> 6, nc = (i & 63) << 2;
            *(float4*)&Ws[kr * 256 + nc] = *(const float4*)&W1[(kt + kr) * 256 + nc];
        }
        __syncthreads();
        #pragma unroll 4
        for (int k = 0; k < 32; ++k) {
            const float* xp = &Xs[(kt + k) * STR2 + 8 * y];
            ulonglong2 xa = *(const ulonglong2*)xp;        // {r0,r0},{r1,r1}
            ulonglong2 xb = *(const ulonglong2*)(xp + 4);  // {r2,r2},{r3,r3}
            #pragma unroll
            for (int j = 0; j < 8; ++j) {
                unsigned long long w =
                    *(const unsigned long long*)&Ws[k * 256 + 2 * x + 32 * j];
                FMA2(acc[0][j], xa.x, w);
                FMA2(acc[1][j], xa.y, w);
                FMA2(acc[2][j], xb.x, w);
                FMA2(acc[3][j], xb.y, w);
            }
        }
    }
    __syncthreads();

    // bias + relu, write H duplicated back into Xs
    #pragma unroll
    for (int j = 0; j < 8; ++j) {
        int c0 = 2 * x + 32 * j;
        float2 bb = *(const float2*)&b1[c0];
        #pragma unroll
        for (int p = 0; p < 4; ++p) {
            float2 s = *reinterpret_cast<float2*>(&acc[p][j]);
            float h0 = fmaxf(s.x + bb.x, 0.f);
            float h1 = fmaxf(s.y + bb.y, 0.f);
            int r = 4 * y + p;
            *(float2*)&Xs[(size_t)c0 * STR2 + 2 * r]       = make_float2(h0, h0);
            *(float2*)&Xs[(size_t)(c0 + 1) * STR2 + 2 * r] = make_float2(h1, h1);
        }
    }
    __syncthreads();

    // ---------------- GEMM2: U[64,128] = relu(H @ W2 + b2), FFMA2 ----------------
    unsigned long long acc2[4][4] = {};

    for (int kt = 0; kt < D_H; kt += 32) {
        __syncthreads();
        #pragma unroll
        for (int i = tid; i < 32 * 32; i += 256) {
            int kr = i >> 5, nc = (i & 31) << 2;
            *(float4*)&Ws[kr * 128 + nc] = *(const float4*)&W2[(kt + kr) * 128 + nc];
        }
        __syncthreads();
        #pragma unroll 4
        for (int k = 0; k < 32; ++k) {
            const float* xp = &Xs[(kt + k) * STR2 + 8 * y];
            ulonglong2 xa = *(const ulonglong2*)xp;
            ulonglong2 xb = *(const ulonglong2*)(xp + 4);
            #pragma unroll
            for (int j = 0; j < 4; ++j) {
                unsigned long long w =
                    *(const unsigned long long*)&Ws[k * 128 + 2 * x + 32 * j];
                FMA2(acc2[0][j], xa.x, w);
                FMA2(acc2[1][j], xa.y, w);
                FMA2(acc2[2][j], xb.x, w);
                FMA2(acc2[3][j], xb.y, w);
            }
        }
    }

    // ---------------- Epilogue: bias + relu + row-normalize + store ----------------
    float h[4][8];
    float sq[4] = {0.f, 0.f, 0.f, 0.f};
    #pragma unroll
    for (int j = 0; j < 4; ++j) {
        int c0 = 2 * x + 32 * j;
        float2 bb = *(const float2*)&b2[c0];
        #pragma unroll
        for (int p = 0; p < 4; ++p) {
            float2 s = *reinterpret_cast<float2*>(&acc2[p][j]);
            float h0 = fmaxf(s.x + bb.x, 0.f);
            float h1 = fmaxf(s.y + bb.y, 0.f);
            h[p][2 * j]     = h0;
            h[p][2 * j + 1] = h1;
            sq[p] = fmaf(h0, h0, fmaf(h1, h1, sq[p]));
        }
    }
    // reduce squared norms across the 16 x-lanes (same warp; bit4 = y parity untouched)
    #pragma unroll
    for (int o = 8; o; o >>= 1) {
        #pragma unroll
        for (int p = 0; p < 4; ++p)
            sq[p] += __shfl_xor_sync(0xffffffffu, sq[p], o);
    }
    float inv[4];
    #pragma unroll
    for (int p = 0; p < 4; ++p)
        inv[p] = 1.f / fmaxf(sqrtf(sq[p]), 1e-8f);

    #pragma unroll
    for (int j = 0; j < 4; ++j) {
        int c0 = 2 * x + 32 * j;
        #pragma unroll
        for (int p = 0; p < 4; ++p) {
            int r = row0 + 4 * y + p;
            *(float2*)&gout[(size_t)r * D_OUT + c0] =
                make_float2(h[p][2 * j] * inv[p], h[p][2 * j + 1] * inv[p]);
        }
    }
}

// ---------------- Scoring on pre-normalized vectors ----------------
// One warp per row; 4 lane-groups of 8 handle the 4 band columns.
__global__ __launch_bounds__(256)
void score_kernel(const int* __restrict__ sw_ids, const float* __restrict__ sw_table,
                  float* __restrict__ out)
{
    int warp = (blockIdx.x * blockDim.x + threadIdx.x) >> 5;
    if (warp >= BATCH) return;
    int lane = threadIdx.x & 31;
    int g    = lane >> 3;      // which band column
    int l8   = lane & 7;

    const float* un = g_uv;
    const float* vn = g_uv + (size_t)BATCH * D_OUT;

    int col = (warp + g) & (BATCH - 1);
    const float4* u4 = (const float4*)&un[(size_t)warp * D_OUT + l8 * 16];
    const float4* v4 = (const float4*)&vn[(size_t)col  * D_OUT + l8 * 16];

    float d = 0.f;
    #pragma unroll
    for (int i = 0; i < 4; ++i) {
        float4 a = u4[i], b = v4[i];
        d = fmaf(a.x, b.x, fmaf(a.y, b.y, fmaf(a.z, b.z, fmaf(a.w, b.w, d))));
    }
    d += __shfl_xor_sync(0xffffffffu, d, 4);
    d += __shfl_xor_sync(0xffffffffu, d, 2);
    d += __shfl_xor_sync(0xffffffffu, d, 1);

    if (l8 == 0)
        out[warp * N_NEG4 + g] =
            d - logf(__ldg(&sw_table[__ldg(&sw_ids[col])]));
}

extern "C" void kernel_launch(void* const* d_in, const int* in_sizes, int n_in,
                              void* d_out, int out_size)
{
    const int*   user_ids    = (const int*)  d_in[0];
    const int*   item_ids    = (const int*)  d_in[1];
    const int*   sw_ids      = (const int*)  d_in[2];
    const float* user_tables = (const float*)d_in[3];
    const float* item_tables = (const float*)d_in[4];
    const float* sw_table    = (const float*)d_in[5];
    const float* uW1 = (const float*)d_in[6];
    const float* ub1 = (const float*)d_in[7];
    const float* uW2 = (const float*)d_in[8];
    const float* ub2 = (const float*)d_in[9];
    const float* iW1 = (const float*)d_in[10];
    const float* ib1 = (const float*)d_in[11];
    const float* iW2 = (const float*)d_in[12];
    const float* ib2 = (const float*)d_in[13];
    (void)in_sizes; (void)n_in; (void)out_size;

    const int smem_bytes = SMEM_FLOATS * (int)sizeof(float);   // 167,936 B
    cudaFuncSetAttribute(tower_kernel, cudaFuncAttributeMaxDynamicSharedMemorySize,
                         smem_bytes);

    tower_kernel<<<128, 256, smem_bytes>>>(user_ids, item_ids,
                                           user_tables, item_tables,
                                           uW1, ub1, uW2, ub2,
                                           iW1, ib1, iW2, ib2);
    score_kernel<<<512, 256>>>(sw_ids, sw_table, (float*)d_out);
}